// round 6
// baseline (speedup 1.0000x reference)
#include <cuda_runtime.h>
#include <cuda_bf16.h>
#include <cstdint>
#include <math.h>

#define NB    2048
#define DD    16
#define EE    256
#define HH    768
#define G3    2304
#define TT    8
#define NPRED 12
#define SCALEF 4.0f

#if defined(__CUDA_ARCH_FEAT_SM103_ALL) || defined(__CUDA_ARCH_FEAT_SM100_ALL) || \
    (defined(__CUDA_ARCH_SPECIFIC__) && (__CUDA_ARCH_SPECIFIC__ >= 1000))
#define HAS_TCG 1
#else
#define HAS_TCG 0
#endif

// ---------------- device scratch ----------------
__device__ __align__(256) __nv_bfloat16 g_Bp1h[G3*HH];
__device__ __align__(256) __nv_bfloat16 g_Bp1l[G3*HH];
__device__ __align__(256) __nv_bfloat16 g_Bp2h[G3*HH];
__device__ __align__(256) __nv_bfloat16 g_Bp2l[G3*HH];
__device__ __align__(256) __nv_bfloat16 g_Bpdh[G3*HH];
__device__ __align__(256) __nv_bfloat16 g_Bpdl[G3*HH];
__device__ __align__(256) __nv_bfloat16 g_Bp2xh[G3*HH];
__device__ __align__(256) __nv_bfloat16 g_Bp2xl[G3*HH];
__device__ __align__(256) __nv_bfloat16 g_Me1_1[G3*32];
__device__ __align__(256) __nv_bfloat16 g_Me2_1[G3*32];
__device__ __align__(256) __nv_bfloat16 g_Me1_2[G3*32];
__device__ __align__(256) __nv_bfloat16 g_Me2_2[G3*32];
__device__ __align__(256) __nv_bfloat16 g_Me1_d[G3*32];
__device__ __align__(256) __nv_bfloat16 g_Me2_d[G3*32];
__device__ __align__(256) float g_bv1[G3];
__device__ __align__(256) float g_bh1[G3];
__device__ __align__(256) float g_bv2[G3];
__device__ __align__(256) float g_bh2[G3];
__device__ __align__(256) float g_bvd[G3];
__device__ __align__(256) float g_bhd[G3];
__device__ __align__(256) __nv_bfloat16 g_A0h[NB*HH];
__device__ __align__(256) __nv_bfloat16 g_A0l[NB*HH];
__device__ __align__(256) __nv_bfloat16 g_A1h[NB*HH];
__device__ __align__(256) __nv_bfloat16 g_A1l[NB*HH];
__device__ __align__(256) float g_C2T[G3*NB];
__device__ __align__(256) float g_h[NB*HH];

// ---------------- helpers ----------------
__device__ __forceinline__ uint32_t smem_u32(const void* p) {
    uint32_t a;
    asm("{ .reg .u64 t; cvta.to.shared.u64 t, %1; cvt.u32.u64 %0, t; }" : "=r"(a) : "l"(p));
    return a;
}
__device__ __forceinline__ uint32_t elect_one() {
    uint32_t pred;
    asm volatile("{\n\t.reg .pred p;\n\telect.sync _|p, 0xFFFFFFFF;\n\t"
                 "selp.b32 %0, 1, 0, p;\n\t}" : "=r"(pred));
    return pred;
}
__device__ __forceinline__ void mbar_init(uint32_t m, uint32_t c) {
    asm volatile("mbarrier.init.shared.b64 [%0], %1;" :: "r"(m), "r"(c) : "memory");
}
__device__ __forceinline__ void mbar_inval(uint32_t m) {
    asm volatile("mbarrier.inval.shared.b64 [%0];" :: "r"(m) : "memory");
}
__device__ __forceinline__ void mbar_wait(uint32_t m, uint32_t par) {
    uint32_t done;
    asm volatile("{\n\t.reg .pred p;\n\t"
        "mbarrier.try_wait.parity.acquire.cta.shared::cta.b64 p, [%1], %2;\n\t"
        "selp.b32 %0, 1, 0, p;\n\t}" : "=r"(done) : "r"(m), "r"(par) : "memory");
    while (!done) {
        asm volatile("{\n\t.reg .pred p;\n\t"
            "mbarrier.try_wait.parity.acquire.cta.shared::cta.b64 p, [%1], %2, 0x989680;\n\t"
            "selp.b32 %0, 1, 0, p;\n\t}" : "=r"(done) : "r"(m), "r"(par) : "memory");
    }
}
#define FENCE_ASYNC_SHARED() asm volatile("fence.proxy.async.shared::cta;" ::: "memory")

__device__ __forceinline__ uint32_t swz64(uint32_t off) { return off ^ ((off >> 3) & 0x30); }
__device__ __forceinline__ uint32_t pack2(__nv_bfloat16 a, __nv_bfloat16 b) {
    __nv_bfloat162 t; t.x = a; t.y = b; return *reinterpret_cast<uint32_t*>(&t);
}
__device__ __forceinline__ int gatemap(int p) {     // permuted row -> original row
    int b = p / 384, rem = p % 384;
    return (rem >> 7) * HH + b * 128 + (rem & 127);
}

#if HAS_TCG
#define TC_ALLOC(s, n)   asm volatile("tcgen05.alloc.cta_group::1.sync.aligned.shared::cta.b32 [%0], %1;" :: "r"(s), "r"((uint32_t)(n)) : "memory")
#define TC_DEALLOC(t, n) asm volatile("tcgen05.dealloc.cta_group::1.sync.aligned.b32 %0, %1;" :: "r"(t), "r"((uint32_t)(n)))
#define TC_RELINQUISH()  asm volatile("tcgen05.relinquish_alloc_permit.cta_group::1.sync.aligned;")
#define TC_COMMIT(m)     asm volatile("tcgen05.commit.cta_group::1.mbarrier::arrive::one.shared::cluster.b64 [%0];" :: "r"(m) : "memory")
#define TC_FENCE_AFTER()  asm volatile("tcgen05.fence::after_thread_sync;" ::: "memory")
#define TC_FENCE_BEFORE() asm volatile("tcgen05.fence::before_thread_sync;" ::: "memory")
#define TC_WAIT_LD()      asm volatile("tcgen05.wait::ld.sync.aligned;" ::: "memory")

#define TC_LD_X16(r, addr) \
    asm volatile("tcgen05.ld.sync.aligned.32x32b.x16.b32 " \
        "{%0, %1, %2, %3, %4, %5, %6, %7, %8, %9, %10, %11, %12, %13, %14, %15}, [%16];" \
        : "=r"((r)[0]),  "=r"((r)[1]),  "=r"((r)[2]),  "=r"((r)[3]), \
          "=r"((r)[4]),  "=r"((r)[5]),  "=r"((r)[6]),  "=r"((r)[7]), \
          "=r"((r)[8]),  "=r"((r)[9]),  "=r"((r)[10]), "=r"((r)[11]), \
          "=r"((r)[12]), "=r"((r)[13]), "=r"((r)[14]), "=r"((r)[15]) \
        : "r"(addr))

__device__ __forceinline__ void mma_bf16_ss(uint32_t d, uint64_t ad, uint64_t bd,
                                            uint32_t idesc, uint32_t en) {
    asm volatile("{\n\t.reg .pred p;\n\tsetp.ne.u32 p, %5, 0;\n\t"
        "tcgen05.mma.cta_group::1.kind::f16 [%0], %1, %2, %3, {%4, %4, %4, %4}, p;\n\t}"
        :: "r"(d), "l"(ad), "l"(bd), "r"(idesc), "r"(0u), "r"(en) : "memory");
}
#define MMA_IDESC ((1u<<4) | (1u<<7) | (1u<<10) | ((128u/8u)<<17) | ((128u/16u)<<24))

// SW64 K-major: layout=4, version=1, SBO=32 (512B atom), LBO=1 (16B)
__device__ __forceinline__ uint64_t desc_sw64(uint32_t addr) {
    const uint64_t base =
        (uint64_t(4) << 61) | (uint64_t(1) << 46) | (uint64_t(32) << 32) | (uint64_t(1) << 16);
    return base | ((uint64_t)(addr >> 4) & 0x3FFF);
}
#endif

// ---------------- fused GEMM+GRU step kernel ----------------
// grid (6, 16), block 256. CTA: rows m*128..+128, hidden block bblk (128 units, 3 gates).
// TMEM: acc0(col0)=r pre, acc1(128)=z pre, acc2(256)=gh_n, acc3(384)=gi_n.
// mode 0: GRU step.  mode 1: plain GEMM, store transposed into c2out[p][row].
#define TILE2  8192
#define STAGE2 (8*TILE2)
#define SM_STG 4096
#define FUSED_SMEM (SM_STG + 3*STAGE2)   // 200704

__global__ void __launch_bounds__(256, 1)
gemm_gru(const __nv_bfloat16* __restrict__ Me1, const __nv_bfloat16* __restrict__ Me2,
         const __nv_bfloat16* __restrict__ Bh,  const __nv_bfloat16* __restrict__ Bl,
         const float* __restrict__ bv, const float* __restrict__ bhhp,
         const float* __restrict__ pa, const float* __restrict__ pb,
         const float* __restrict__ C2T,
         const __nv_bfloat16* __restrict__ Ainh, const __nv_bfloat16* __restrict__ Ainl,
         float* __restrict__ hbuf,
         __nv_bfloat16* __restrict__ oAh, __nv_bfloat16* __restrict__ oAl,
         float* __restrict__ c2out,
         int hasH, int useC2, int mode) {
    extern __shared__ char smem[];
    int tid = threadIdx.x, wid = tid >> 5, lane = tid & 31;
    int bblk = blockIdx.x, m = blockIdx.y;
    int nchunks = (mode == 1) ? 24 : (hasH ? 26 : 2);
#if HAS_TCG
    uint32_t sb = smem_u32(smem);
    float* bs = (float*)(smem + 64);
    float* bh2s = (float*)(smem + 1600);

    if (wid == 0) TC_ALLOC(sb, 512);
    if (tid == 0) { mbar_init(sb+16,1); mbar_init(sb+24,1); mbar_init(sb+32,1); }
    if (mode == 0) {
        for (int x = tid; x < 384; x += 256) {
            bs[x]  = bv[bblk*384 + x];
            bh2s[x] = bhhp[bblk*384 + x];
        }
    }
    __syncthreads();
    uint32_t tmem;
    asm volatile("ld.shared.b32 %0, [%1];" : "=r"(tmem) : "r"(sb));

    int row = tid >> 1, part = tid & 1;
    uint32_t base = row * 64 + part * 32;
    uint32_t o0 = swz64(base), o1 = swz64(base + 16);

    for (int i = 0; i < nchunks; i++) {
        int slot = i % 3;
        char* stg = smem + SM_STG + slot * STAGE2;
        uint32_t stgu = sb + SM_STG + slot * STAGE2;
        if (i >= 3) mbar_wait(sb + 16 + slot*8, ((i - 3) / 3) & 1);

        int isExt = (mode == 0) && (i < 2);
        if (isExt) {
            const float* par = pa + (size_t)(m*128 + row) * DD;
            const float* pbr = pb + (size_t)(m*128 + row) * DD;
            uint32_t w[8];
            #pragma unroll
            for (int e = 0; e < 8; e++) {
                float x0 = par[2*e]   - pbr[2*e];
                float x1 = par[2*e+1] - pbr[2*e+1];
                __nv_bfloat16 h0 = __float2bfloat16(x0);
                __nv_bfloat16 h1 = __float2bfloat16(x1);
                if (i == 0) {
                    w[e] = pack2(h0, h1);
                } else if (part == 0) {
                    w[e] = pack2(__float2bfloat16(x0 - __bfloat162float(h0)),
                                 __float2bfloat16(x1 - __bfloat162float(h1)));
                } else w[e] = 0u;
            }
            *(uint4*)(stg + o0) = make_uint4(w[0], w[1], w[2], w[3]);
            *(uint4*)(stg + o1) = make_uint4(w[4], w[5], w[6], w[7]);
            const __nv_bfloat16* Me = (i == 0) ? Me1 : Me2;
            #pragma unroll
            for (int g = 0; g < 3; g++) {
                const uint4* src = (const uint4*)(Me + (size_t)(bblk*384 + g*128 + row)*32 + part*16);
                char* dt = stg + (2 + g*2) * TILE2;
                *(uint4*)(dt + o0) = src[0];
                *(uint4*)(dt + o1) = src[1];
            }
        } else {
            int ih = i - ((mode == 0) ? 2 : 0);
            int kc = ih * 32;
            size_t ao = (size_t)(m*128 + row) * HH + kc + part*16;
            const uint4* sh = (const uint4*)(Ainh + ao);
            const uint4* sl = (const uint4*)(Ainl + ao);
            *(uint4*)(stg + o0) = sh[0];
            *(uint4*)(stg + o1) = sh[1];
            *(uint4*)(stg + TILE2 + o0) = sl[0];
            *(uint4*)(stg + TILE2 + o1) = sl[1];
            #pragma unroll
            for (int g = 0; g < 3; g++) {
                size_t bo = (size_t)(bblk*384 + g*128 + row) * HH + kc + part*16;
                const uint4* bhp = (const uint4*)(Bh + bo);
                const uint4* blp = (const uint4*)(Bl + bo);
                char* dh = stg + (2 + g*2) * TILE2;
                char* dl = stg + (3 + g*2) * TILE2;
                *(uint4*)(dh + o0) = bhp[0];
                *(uint4*)(dh + o1) = bhp[1];
                *(uint4*)(dl + o0) = blp[0];
                *(uint4*)(dl + o1) = blp[1];
            }
        }
        FENCE_ASYNC_SHARED();
        __syncthreads();

        if (wid == 0 && elect_one()) {
            uint64_t dA0 = desc_sw64(stgu);
            uint64_t dA1 = desc_sw64(stgu + TILE2);
            if (isExt) {
                #pragma unroll
                for (int g = 0; g < 3; g++) {
                    uint32_t acc = tmem + ((g == 2) ? 384 : g*128);
                    uint64_t dB = desc_sw64(stgu + (2 + g*2) * TILE2);
                    if (i == 0) {
                        mma_bf16_ss(acc, dA0,     dB,     MMA_IDESC, 0u);
                        mma_bf16_ss(acc, dA0 + 2, dB + 2, MMA_IDESC, 1u);
                    } else {
                        mma_bf16_ss(acc, dA0, dB, MMA_IDESC, 1u);
                    }
                }
            } else {
                int firstH = (i == ((mode == 0) ? 2 : 0));
                #pragma unroll
                for (int s = 0; s < 2; s++) {
                    uint64_t o = (uint64_t)(s * 2);
                    #pragma unroll
                    for (int g = 0; g < 3; g++) {
                        uint32_t acc = tmem + g*128;
                        uint64_t dBh = desc_sw64(stgu + (2 + g*2) * TILE2);
                        uint64_t dBl = desc_sw64(stgu + (3 + g*2) * TILE2);
                        uint32_t en0;
                        if (mode == 1) en0 = (firstH && s == 0) ? 0u : 1u;
                        else           en0 = (g == 2 && firstH && s == 0) ? 0u : 1u;
                        mma_bf16_ss(acc, dA0 + o, dBh + o, MMA_IDESC, en0);
                        mma_bf16_ss(acc, dA0 + o, dBl + o, MMA_IDESC, 1u);
                        mma_bf16_ss(acc, dA1 + o, dBh + o, MMA_IDESC, 1u);
                    }
                }
            }
            TC_COMMIT(sb + 16 + slot*8);
        }
    }

    int L = nchunks - 1;
    mbar_wait(sb + 16 + (L % 3)*8, (L / 3) & 1);
    TC_FENCE_AFTER();

    int sub = wid & 3, half = wid >> 2;
    int rowl = sub*32 + lane, rowg = m*128 + rowl;

    if (mode == 1) {
        #pragma unroll
        for (int g = 0; g < 3; g++) {
            #pragma unroll
            for (int b2 = 0; b2 < 4; b2++) {
                int c0 = half*64 + b2*16;
                uint32_t u[16];
                TC_LD_X16(u, tmem + g*128 + c0);
                TC_WAIT_LD();
                #pragma unroll
                for (int e = 0; e < 16; e++)
                    c2out[(size_t)(bblk*384 + g*128 + c0 + e) * NB + rowg] = __uint_as_float(u[e]);
            }
        }
    } else {
        float* hrow = hbuf + (size_t)rowg * HH + bblk*128;
        __nv_bfloat16* ahr = oAh + (size_t)rowg * HH + bblk*128;
        __nv_bfloat16* alr = oAl + (size_t)rowg * HH + bblk*128;
        #pragma unroll
        for (int b2 = 0; b2 < 4; b2++) {
            int c0 = half*64 + b2*16;
            uint32_t ur[16], uz[16], un[16], ui[16];
            TC_LD_X16(ur, tmem + c0);
            TC_LD_X16(uz, tmem + 128 + c0);
            TC_LD_X16(ui, tmem + 384 + c0);
            if (hasH) TC_LD_X16(un, tmem + 256 + c0);
            TC_WAIT_LD();
            float hv[16];
            if (hasH) {
                #pragma unroll
                for (int q = 0; q < 4; q++)
                    *(float4*)(hv + q*4) = *(const float4*)(hrow + c0 + q*4);
            } else {
                #pragma unroll
                for (int e = 0; e < 16; e++) hv[e] = 0.0f;
            }
            #pragma unroll
            for (int e = 0; e < 16; e++) {
                int cc = c0 + e;
                float rpre = __uint_as_float(ur[e]) + bs[cc]      + bh2s[cc];
                float zpre = __uint_as_float(uz[e]) + bs[128+cc]  + bh2s[128+cc];
                float ghn  = (hasH ? __uint_as_float(un[e]) : 0.0f) + bh2s[256+cc];
                float gin  = __uint_as_float(ui[e]) + bs[256+cc];
                if (useC2) {
                    rpre += C2T[(size_t)(bblk*384 + cc)       * NB + rowg];
                    zpre += C2T[(size_t)(bblk*384 + 128 + cc) * NB + rowg];
                    gin  += C2T[(size_t)(bblk*384 + 256 + cc) * NB + rowg];
                }
                float r = 1.0f / (1.0f + expf(-rpre));
                float z = 1.0f / (1.0f + expf(-zpre));
                float n = tanhf(gin + r * ghn);
                hv[e] = (1.0f - z) * n + z * hv[e];
            }
            uint32_t wh[8], wl[8];
            #pragma unroll
            for (int q = 0; q < 8; q++) {
                __nv_bfloat16 h0 = __float2bfloat16(hv[2*q]);
                __nv_bfloat16 h1 = __float2bfloat16(hv[2*q+1]);
                wh[q] = pack2(h0, h1);
                wl[q] = pack2(__float2bfloat16(hv[2*q]   - __bfloat162float(h0)),
                              __float2bfloat16(hv[2*q+1] - __bfloat162float(h1)));
            }
            #pragma unroll
            for (int q = 0; q < 4; q++)
                *(float4*)(hrow + c0 + q*4) = *(float4*)(hv + q*4);
            *(uint4*)(ahr + c0)     = make_uint4(wh[0], wh[1], wh[2], wh[3]);
            *(uint4*)(ahr + c0 + 8) = make_uint4(wh[4], wh[5], wh[6], wh[7]);
            *(uint4*)(alr + c0)     = make_uint4(wl[0], wl[1], wl[2], wl[3]);
            *(uint4*)(alr + c0 + 8) = make_uint4(wl[4], wl[5], wl[6], wl[7]);
        }
    }
    TC_FENCE_BEFORE();
    __syncthreads();
    if (tid == 0) { mbar_inval(sb+16); mbar_inval(sb+24); mbar_inval(sb+32); }
    __syncthreads();
    if (wid == 0) { TC_RELINQUISH(); TC_DEALLOC(tmem, 512); }
#else
    // ---- naive fallback (plain sm_103 device pass; never selected on GB300) ----
    for (int u = tid; u < 128*128; u += 256) {
        int rowl = u >> 7, jj = u & 127;
        int rowg = m*128 + rowl;
        float dots[3] = {0.f, 0.f, 0.f};
        int doDot = (mode == 1) || hasH;
        if (doDot) {
            const __nv_bfloat16* arh = Ainh + (size_t)rowg * HH;
            const __nv_bfloat16* arl = Ainl + (size_t)rowg * HH;
            for (int g = 0; g < 3; g++) {
                size_t pr = (size_t)(bblk*384 + g*128 + jj) * HH;
                float s = 0.f;
                for (int k = 0; k < HH; k++) {
                    float a = __bfloat162float(arh[k]) + __bfloat162float(arl[k]);
                    float b = __bfloat162float(Bh[pr + k]) + __bfloat162float(Bl[pr + k]);
                    s += a * b;
                }
                dots[g] = s;
            }
        }
        if (mode == 1) {
            for (int g = 0; g < 3; g++)
                c2out[(size_t)(bblk*384 + g*128 + jj) * NB + rowg] = dots[g];
            continue;
        }
        float v[DD];
        for (int d = 0; d < DD; d++)
            v[d] = pa[(size_t)rowg*DD + d] - pb[(size_t)rowg*DD + d];
        float gi[3];
        for (int g = 0; g < 3; g++) {
            int p = bblk*384 + g*128 + jj;
            float s = bv[p];
            for (int d = 0; d < DD; d++) {
                float mm = __bfloat162float(Me1[(size_t)p*32 + d]) +
                           __bfloat162float(Me1[(size_t)p*32 + 16 + d]);
                s += v[d] * mm;
            }
            if (useC2) s += C2T[(size_t)p * NB + rowg];
            gi[g] = s;
        }
        int p0 = bblk*384 + jj;
        float rpre = gi[0] + dots[0] + bhhp[p0];
        float zpre = gi[1] + dots[1] + bhhp[p0 + 128];
        float ghn  = dots[2] + bhhp[p0 + 256];
        float r = 1.0f / (1.0f + expf(-rpre));
        float z = 1.0f / (1.0f + expf(-zpre));
        float n = tanhf(gi[2] + r * ghn);
        size_t hi = (size_t)rowg * HH + bblk*128 + jj;
        float hold = hasH ? hbuf[hi] : 0.0f;
        float hn = (1.0f - z) * n + z * hold;
        hbuf[hi] = hn;
        __nv_bfloat16 hb = __float2bfloat16(hn);
        oAh[hi] = hb;
        oAl[hi] = __float2bfloat16(hn - __bfloat162float(hb));
    }
#endif
}

// ---------------- prep kernels ----------------
__global__ void perm_conv(const float* __restrict__ W, int ldw, int off,
                          __nv_bfloat16* __restrict__ oh, __nv_bfloat16* __restrict__ ol) {
    int idx = blockIdx.x * blockDim.x + threadIdx.x;
    if (idx >= G3 * HH) return;
    int p = idx / HH, k = idx % HH;
    int c = gatemap(p);
    float x = W[(size_t)c * ldw + off + k];
    __nv_bfloat16 h = __float2bfloat16(x);
    oh[idx] = h;
    ol[idx] = __float2bfloat16(x - __bfloat162float(h));
}

__global__ void prep_ext(const float* __restrict__ Wih, int ldw,
                         const float* __restrict__ bih,
                         const float* __restrict__ embW, const float* __restrict__ embB,
                         const float* __restrict__ bhh_in,
                         __nv_bfloat16* __restrict__ Me1, __nv_bfloat16* __restrict__ Me2,
                         float* __restrict__ bvp, float* __restrict__ bhp) {
    int p = blockIdx.x * blockDim.x + threadIdx.x;
    if (p >= G3) return;
    int c = gatemap(p);
    const float* wrow = Wih + (size_t)c * ldw;
    float acc[DD];
    #pragma unroll
    for (int d = 0; d < DD; d++) acc[d] = 0.0f;
    float ab = 0.0f;
    for (int e = 0; e < EE; e++) {
        float w = wrow[e];
        ab += embB[e] * w;
        const float* er = embW + e * DD;
        #pragma unroll
        for (int d = 0; d < DD; d++) acc[d] += er[d] * w;
    }
    bvp[p] = bih[c] + ab;
    bhp[p] = bhh_in[c];
    #pragma unroll
    for (int d = 0; d < DD; d++) {
        float x = SCALEF * acc[d];
        __nv_bfloat16 hi = __float2bfloat16(x);
        __nv_bfloat16 lo = __float2bfloat16(x - __bfloat162float(hi));
        Me1[(size_t)p*32 + d]      = hi;
        Me1[(size_t)p*32 + 16 + d] = lo;
        Me2[(size_t)p*32 + d]      = hi;
        Me2[(size_t)p*32 + 16 + d] = __float2bfloat16(0.0f);
    }
}

// ---------------- decoder head ----------------
__global__ void h2n_pos(const float* __restrict__ h,
                        const float* __restrict__ h2nW, const float* __restrict__ h2nB,
                        const float* __restrict__ mixW, const float* __restrict__ mixB,
                        const float* __restrict__ base,
                        float* __restrict__ out_rel, float* __restrict__ out_pos) {
    int row = blockIdx.x;
    int tid = threadIdx.x;
    int warp = tid >> 5, lane = tid & 31;
    __shared__ float sn[5];
    if (warp < 5) {
        const float* hr = h + (size_t)row * HH;
        const float* wr = h2nW + warp * HH;
        float s = 0.0f;
        for (int i = lane; i < HH; i += 32) s = fmaf(hr[i], wr[i], s);
        #pragma unroll
        for (int o = 16; o > 0; o >>= 1) s += __shfl_down_sync(0xffffffffu, s, o);
        if (lane == 0) {
            float raw = s + h2nB[warp];
            float val;
            if (warp < 2) val = raw;
            else if (warp < 4) {
                float sp = raw > 0.0f ? raw + log1pf(expf(-raw)) : log1pf(expf(raw));
                val = 0.01f + 0.2f * sp;
            } else val = 0.7f * tanhf(raw);
            sn[warp] = val;
            out_rel[(size_t)row * 5 + warp] = val;
        }
    }
    __syncthreads();
    if (tid < DD) {
        float acc = mixB[tid];
        #pragma unroll
        for (int c = 0; c < 5; c++) acc = fmaf(sn[c], mixW[tid * 5 + c], acc);
        acc = acc > 0.0f ? acc : 0.0f;
        out_pos[(size_t)row * DD + tid] = base[(size_t)row * DD + tid] + acc;
    }
}

// ---------------- host ----------------
extern "C" void kernel_launch(void* const* d_in, const int* in_sizes, int n_in,
                              void* d_out, int out_size) {
    const float* observed = (const float*)d_in[0];
    const float* emb_W    = (const float*)d_in[1];
    const float* emb_b    = (const float*)d_in[2];
    const float* e1_Wih   = (const float*)d_in[3];
    const float* e1_Whh   = (const float*)d_in[4];
    const float* e1_bih   = (const float*)d_in[5];
    const float* e1_bhh   = (const float*)d_in[6];
    const float* e2_Wih   = (const float*)d_in[7];
    const float* e2_Whh   = (const float*)d_in[8];
    const float* e2_bih   = (const float*)d_in[9];
    const float* e2_bhh   = (const float*)d_in[10];
    const float* dec_Wih  = (const float*)d_in[11];
    const float* dec_Whh  = (const float*)d_in[12];
    const float* dec_bih  = (const float*)d_in[13];
    const float* dec_bhh  = (const float*)d_in[14];
    const float* h2n_W    = (const float*)d_in[15];
    const float* h2n_b    = (const float*)d_in[16];
    const float* mix_W    = (const float*)d_in[17];
    const float* mix_b    = (const float*)d_in[18];
    float* out = (float*)d_out;

    __nv_bfloat16 *B1h,*B1l,*B2h,*B2l,*Bdh,*Bdl,*B2xh,*B2xl;
    __nv_bfloat16 *Me11,*Me21,*Me12,*Me22,*Me1d,*Me2d;
    __nv_bfloat16 *A0h,*A0l,*A1h,*A1l;
    float *bv1,*bh1,*bv2,*bh2,*bvd,*bhd,*C2T,*h;
    cudaGetSymbolAddress((void**)&B1h, g_Bp1h);   cudaGetSymbolAddress((void**)&B1l, g_Bp1l);
    cudaGetSymbolAddress((void**)&B2h, g_Bp2h);   cudaGetSymbolAddress((void**)&B2l, g_Bp2l);
    cudaGetSymbolAddress((void**)&Bdh, g_Bpdh);   cudaGetSymbolAddress((void**)&Bdl, g_Bpdl);
    cudaGetSymbolAddress((void**)&B2xh,g_Bp2xh);  cudaGetSymbolAddress((void**)&B2xl,g_Bp2xl);
    cudaGetSymbolAddress((void**)&Me11,g_Me1_1);  cudaGetSymbolAddress((void**)&Me21,g_Me2_1);
    cudaGetSymbolAddress((void**)&Me12,g_Me1_2);  cudaGetSymbolAddress((void**)&Me22,g_Me2_2);
    cudaGetSymbolAddress((void**)&Me1d,g_Me1_d);  cudaGetSymbolAddress((void**)&Me2d,g_Me2_d);
    cudaGetSymbolAddress((void**)&A0h, g_A0h);    cudaGetSymbolAddress((void**)&A0l, g_A0l);
    cudaGetSymbolAddress((void**)&A1h, g_A1h);    cudaGetSymbolAddress((void**)&A1l, g_A1l);
    cudaGetSymbolAddress((void**)&bv1, g_bv1);    cudaGetSymbolAddress((void**)&bh1, g_bh1);
    cudaGetSymbolAddress((void**)&bv2, g_bv2);    cudaGetSymbolAddress((void**)&bh2, g_bh2);
    cudaGetSymbolAddress((void**)&bvd, g_bvd);    cudaGetSymbolAddress((void**)&bhd, g_bhd);
    cudaGetSymbolAddress((void**)&C2T, g_C2T);
    cudaGetSymbolAddress((void**)&h,   g_h);

    cudaFuncSetAttribute(gemm_gru, cudaFuncAttributeMaxDynamicSharedMemorySize, FUSED_SMEM);

    const int ND = NB * DD;
    float* rel_out  = out;
    float* pred_out = out + (size_t)NPRED * NB * 5;

    dim3 grid(G3 / 384, NB / 128);   // (6,16)
    const int WELEM = G3 * HH;

    perm_conv<<<(WELEM+255)/256, 256>>>(e1_Whh,  HH,      0,  B1h,  B1l);
    perm_conv<<<(WELEM+255)/256, 256>>>(e2_Whh,  HH,      0,  B2h,  B2l);
    perm_conv<<<(WELEM+255)/256, 256>>>(dec_Whh, HH,      0,  Bdh,  Bdl);
    perm_conv<<<(WELEM+255)/256, 256>>>(e2_Wih,  EE + HH, EE, B2xh, B2xl);
    prep_ext<<<(G3+255)/256, 256>>>(e1_Wih,  EE,      e1_bih,  emb_W, emb_b, e1_bhh,  Me11, Me21, bv1, bh1);
    prep_ext<<<(G3+255)/256, 256>>>(e2_Wih,  EE + HH, e2_bih,  emb_W, emb_b, e2_bhh,  Me12, Me22, bv2, bh2);
    prep_ext<<<(G3+255)/256, 256>>>(dec_Wih, EE,      dec_bih, emb_W, emb_b, dec_bhh, Me1d, Me2d, bvd, bhd);

    __nv_bfloat16* Abuf[2][2] = {{A0h, A0l}, {A1h, A1l}};
    int cur = 0;

    // encoder 1 (backward velocities)
    for (int t = 0; t < TT - 1; t++) {
        const float* pa = observed + (size_t)(7 - t) * ND;
        const float* pb = observed + (size_t)(6 - t) * ND;
        gemm_gru<<<grid, 256, FUSED_SMEM>>>(Me11, Me21, B1h, B1l, bv1, bh1, pa, pb,
            nullptr, Abuf[cur][0], Abuf[cur][1], h, Abuf[1-cur][0], Abuf[1-cur][1],
            nullptr, (t > 0) ? 1 : 0, 0, 0);
        cur ^= 1;
    }
    // C2T = h_inv @ e2_Wih[:,256:]^T (permuted, transposed store)
    gemm_gru<<<grid, 256, FUSED_SMEM>>>(nullptr, nullptr, B2xh, B2xl, nullptr, nullptr,
        nullptr, nullptr, nullptr, Abuf[cur][0], Abuf[cur][1], h,
        Abuf[1-cur][0], Abuf[1-cur][1], C2T, 1, 0, 1);

    // encoder 2 (forward velocities)
    for (int t = 0; t < TT - 1; t++) {
        const float* pa = observed + (size_t)(t + 1) * ND;
        const float* pb = observed + (size_t)t * ND;
        gemm_gru<<<grid, 256, FUSED_SMEM>>>(Me12, Me22, B2h, B2l, bv2, bh2, pa, pb,
            C2T, Abuf[cur][0], Abuf[cur][1], h, Abuf[1-cur][0], Abuf[1-cur][1],
            nullptr, (t > 0) ? 1 : 0, 1, 0);
        cur ^= 1;
    }

    // decoder
    for (int k = 0; k < NPRED; k++) {
        const float *pa, *pb;
        if (k == 0)      { pa = observed + (size_t)7 * ND; pb = observed + (size_t)6 * ND; }
        else if (k == 1) { pa = pred_out;                  pb = observed + (size_t)7 * ND; }
        else             { pa = pred_out + (size_t)(k-1)*ND; pb = pred_out + (size_t)(k-2)*ND; }
        gemm_gru<<<grid, 256, FUSED_SMEM>>>(Me1d, Me2d, Bdh, Bdl, bvd, bhd, pa, pb,
            nullptr, Abuf[cur][0], Abuf[cur][1], h, Abuf[1-cur][0], Abuf[1-cur][1],
            nullptr, 1, 0, 0);
        cur ^= 1;
        h2n_pos<<<NB, 160>>>(h, h2n_W, h2n_b, mix_W, mix_b, pa,
                             rel_out + (size_t)k * NB * 5,
                             pred_out + (size_t)k * ND);
    }
}

// round 7
// speedup vs baseline: 1.6626x; 1.6626x over previous
#include <cuda_runtime.h>
#include <cuda.h>
#include <cuda_bf16.h>
#include <cstdint>
#include <math.h>

#define NB    2048
#define DD    16
#define EE    256
#define HH    768
#define G3    2304
#define TT    8
#define NPRED 12
#define SCALEF 4.0f

#if defined(__CUDA_ARCH_FEAT_SM103_ALL) || defined(__CUDA_ARCH_FEAT_SM100_ALL) || \
    (defined(__CUDA_ARCH_SPECIFIC__) && (__CUDA_ARCH_SPECIFIC__ >= 1000))
#define HAS_TCG 1
#else
#define HAS_TCG 0
#endif

// ---------------- device scratch ----------------
__device__ __align__(256) float g_M1[DD*G3];
__device__ __align__(256) float g_M2[DD*G3];
__device__ __align__(256) float g_Md[DD*G3];
__device__ __align__(256) float g_b1[G3];
__device__ __align__(256) float g_b2[G3];
__device__ __align__(256) float g_bd[G3];
__device__ __align__(256) __nv_bfloat16 g_Bh1[G3*HH];
__device__ __align__(256) __nv_bfloat16 g_Bl1[G3*HH];
__device__ __align__(256) __nv_bfloat16 g_Bh2[G3*HH];
__device__ __align__(256) __nv_bfloat16 g_Bl2[G3*HH];
__device__ __align__(256) __nv_bfloat16 g_Bhd[G3*HH];
__device__ __align__(256) __nv_bfloat16 g_Bld[G3*HH];
__device__ __align__(256) __nv_bfloat16 g_Bh2x[G3*HH];
__device__ __align__(256) __nv_bfloat16 g_Bl2x[G3*HH];
__device__ __align__(256) __nv_bfloat16 g_Ah[NB*HH];
__device__ __align__(256) __nv_bfloat16 g_Al[NB*HH];
__device__ __align__(256) float g_C2[NB*G3];
__device__ __align__(256) float g_G[NB*G3];
__device__ __align__(256) float g_h[NB*HH];

// ---------------- helpers ----------------
__device__ __forceinline__ uint32_t smem_u32(const void* p) {
    uint32_t a;
    asm("{ .reg .u64 t; cvta.to.shared.u64 t, %1; cvt.u32.u64 %0, t; }" : "=r"(a) : "l"(p));
    return a;
}
__device__ __forceinline__ uint32_t elect_one() {
    uint32_t pred;
    asm volatile("{\n\t.reg .pred p;\n\telect.sync _|p, 0xFFFFFFFF;\n\t"
                 "selp.b32 %0, 1, 0, p;\n\t}" : "=r"(pred));
    return pred;
}
__device__ __forceinline__ void mbar_init(uint32_t m, uint32_t c) {
    asm volatile("mbarrier.init.shared.b64 [%0], %1;" :: "r"(m), "r"(c) : "memory");
}
__device__ __forceinline__ void mbar_inval(uint32_t m) {
    asm volatile("mbarrier.inval.shared.b64 [%0];" :: "r"(m) : "memory");
}
__device__ __forceinline__ void mbar_wait(uint32_t m, uint32_t par) {
    uint32_t done;
    asm volatile("{\n\t.reg .pred p;\n\t"
        "mbarrier.try_wait.parity.acquire.cta.shared::cta.b64 p, [%1], %2;\n\t"
        "selp.b32 %0, 1, 0, p;\n\t}" : "=r"(done) : "r"(m), "r"(par) : "memory");
    while (!done) {
        asm volatile("{\n\t.reg .pred p;\n\t"
            "mbarrier.try_wait.parity.acquire.cta.shared::cta.b64 p, [%1], %2, 0x989680;\n\t"
            "selp.b32 %0, 1, 0, p;\n\t}" : "=r"(done) : "r"(m), "r"(par) : "memory");
    }
}

#if HAS_TCG
#define TC_ALLOC(s, n)   asm volatile("tcgen05.alloc.cta_group::1.sync.aligned.shared::cta.b32 [%0], %1;" :: "r"(s), "r"((uint32_t)(n)) : "memory")
#define TC_DEALLOC(t, n) asm volatile("tcgen05.dealloc.cta_group::1.sync.aligned.b32 %0, %1;" :: "r"(t), "r"((uint32_t)(n)))
#define TC_RELINQUISH()  asm volatile("tcgen05.relinquish_alloc_permit.cta_group::1.sync.aligned;")
#define TC_COMMIT(m)     asm volatile("tcgen05.commit.cta_group::1.mbarrier::arrive::one.shared::cluster.b64 [%0];" :: "r"(m) : "memory")
#define TC_FENCE_AFTER()  asm volatile("tcgen05.fence::after_thread_sync;" ::: "memory")
#define TC_FENCE_BEFORE() asm volatile("tcgen05.fence::before_thread_sync;" ::: "memory")
#define TC_WAIT_LD()      asm volatile("tcgen05.wait::ld.sync.aligned;" ::: "memory")

#define TC_LD_X32(r, addr) \
    asm volatile("tcgen05.ld.sync.aligned.32x32b.x32.b32 " \
        "{%0, %1, %2, %3, %4, %5, %6, %7, " \
        " %8, %9, %10, %11, %12, %13, %14, %15, " \
        " %16, %17, %18, %19, %20, %21, %22, %23, " \
        " %24, %25, %26, %27, %28, %29, %30, %31}, [%32];" \
        : "=r"((r)[0]),  "=r"((r)[1]),  "=r"((r)[2]),  "=r"((r)[3]), \
          "=r"((r)[4]),  "=r"((r)[5]),  "=r"((r)[6]),  "=r"((r)[7]), \
          "=r"((r)[8]),  "=r"((r)[9]),  "=r"((r)[10]), "=r"((r)[11]), \
          "=r"((r)[12]), "=r"((r)[13]), "=r"((r)[14]), "=r"((r)[15]), \
          "=r"((r)[16]), "=r"((r)[17]), "=r"((r)[18]), "=r"((r)[19]), \
          "=r"((r)[20]), "=r"((r)[21]), "=r"((r)[22]), "=r"((r)[23]), \
          "=r"((r)[24]), "=r"((r)[25]), "=r"((r)[26]), "=r"((r)[27]), \
          "=r"((r)[28]), "=r"((r)[29]), "=r"((r)[30]), "=r"((r)[31]) \
        : "r"(addr))

__device__ __forceinline__ void mma_bf16_ss(uint32_t d, uint64_t ad, uint64_t bd,
                                            uint32_t idesc, uint32_t en) {
    asm volatile("{\n\t.reg .pred p;\n\tsetp.ne.u32 p, %5, 0;\n\t"
        "tcgen05.mma.cta_group::1.kind::f16 [%0], %1, %2, %3, {%4, %4, %4, %4}, p;\n\t}"
        :: "r"(d), "l"(ad), "l"(bd), "r"(idesc), "r"(0u), "r"(en) : "memory");
}
#define MMA_IDESC ((1u<<4) | (1u<<7) | (1u<<10) | ((128u/8u)<<17) | ((128u/16u)<<24))

__device__ __forceinline__ uint64_t make_desc_sw128(uint32_t addr) {
    const uint64_t base =
        (uint64_t(2) << 61) | (uint64_t(1) << 46) | (uint64_t(64) << 32) | (uint64_t(1) << 16);
    return base | ((uint64_t)(addr >> 4) & 0x3FFF);
}

#define MBAR_EXPECT_TX(m, bytes) \
    asm volatile("mbarrier.arrive.expect_tx.shared.b64 _, [%0], %1;" \
                 :: "r"(m), "r"((uint32_t)(bytes)) : "memory")
#define TMA_LD_2D(dst, map, x, y, mbar) \
    asm volatile("cp.async.bulk.tensor.2d.shared::cta.global.tile.mbarrier::complete_tx::bytes " \
                 "[%0], [%1, {%2, %3}], [%4];" \
                 :: "r"(dst), "l"(map), "r"(x), "r"(y), "r"(mbar) : "memory")
#endif

// ---------------- GEMM: C(2048x2304) = A(2048x768) @ B(2304x768)^T -----------
// TMA-fed double-buffered tcgen05 pipeline. 3xbf16 emulation.
// CTA tile M=128, N=256 -> grid (9,16) = 144 CTAs, 1 wave.
#define KC      64
#define NCHUNK  (HH / KC)             // 12
#define TILEB   16384                 // 128 rows x 128B (SW128 box 64 bf16 x 128)
#define STAGEB  (6 * TILEB)           // Ah, Al, Bh0, Bl0, Bh1, Bl1
#define GEMM_SMEM (1024 + 2 * STAGEB) // 197632

__global__ void __launch_bounds__(256, 1)
gemm_tc(const __grid_constant__ CUtensorMap mAh, const __grid_constant__ CUtensorMap mAl,
        const __grid_constant__ CUtensorMap mBh, const __grid_constant__ CUtensorMap mBl,
        const __nv_bfloat16* __restrict__ Ahg, const __nv_bfloat16* __restrict__ Alg,
        const __nv_bfloat16* __restrict__ Bhg, const __nv_bfloat16* __restrict__ Blg,
        float* __restrict__ C) {
    extern __shared__ char smem[];
    int tid = threadIdx.x, wid = tid >> 5, lane = tid & 31;
#if HAS_TCG
    uint32_t sb = smem_u32(smem);
    // mbars: full0=sb+16, full1=sb+24, empty0=sb+32, empty1=sb+40
    if (wid == 0) TC_ALLOC(sb, 512);
    if (tid == 0) {
        mbar_init(sb+16,1); mbar_init(sb+24,1);
        mbar_init(sb+32,1); mbar_init(sb+40,1);
    }
    __syncthreads();
    uint32_t tmem;
    asm volatile("ld.shared.b32 %0, [%1];" : "=r"(tmem) : "r"(sb));

    if (wid == 0 && elect_one()) {
        int arow = blockIdx.y * 128;
        int brow = blockIdx.x * 256;
        for (int i = 0; i < NCHUNK; i++) {
            int slot = i & 1;
            uint32_t stgu = sb + 1024 + slot * STAGEB;
            uint32_t fb = sb + 16 + 8 * slot;
            uint32_t eb = sb + 32 + 8 * slot;
            if (i >= 2) mbar_wait(eb, ((i - 2) >> 1) & 1);

            int kc0 = i * KC;
            MBAR_EXPECT_TX(fb, 6 * TILEB);
            TMA_LD_2D(stgu,             &mAh, kc0, arow,       fb);
            TMA_LD_2D(stgu + TILEB,     &mAl, kc0, arow,       fb);
            TMA_LD_2D(stgu + 2*TILEB,   &mBh, kc0, brow,       fb);
            TMA_LD_2D(stgu + 3*TILEB,   &mBl, kc0, brow,       fb);
            TMA_LD_2D(stgu + 4*TILEB,   &mBh, kc0, brow + 128, fb);
            TMA_LD_2D(stgu + 5*TILEB,   &mBl, kc0, brow + 128, fb);
            mbar_wait(fb, (i >> 1) & 1);

            uint64_t dAh  = make_desc_sw128(stgu);
            uint64_t dAl  = make_desc_sw128(stgu + TILEB);
            uint64_t dBh0 = make_desc_sw128(stgu + 2*TILEB);
            uint64_t dBl0 = make_desc_sw128(stgu + 3*TILEB);
            uint64_t dBh1 = make_desc_sw128(stgu + 4*TILEB);
            uint64_t dBl1 = make_desc_sw128(stgu + 5*TILEB);
            uint32_t first = (i == 0) ? 0u : 1u;
            #pragma unroll
            for (int s = 0; s < 4; s++) {   // K=16 per MMA, +32B per step
                uint64_t o = (uint64_t)(s * 2);
                uint32_t en0 = (s == 0) ? first : 1u;
                mma_bf16_ss(tmem,       dAh + o, dBh0 + o, MMA_IDESC, en0);
                mma_bf16_ss(tmem,       dAh + o, dBl0 + o, MMA_IDESC, 1u);
                mma_bf16_ss(tmem,       dAl + o, dBh0 + o, MMA_IDESC, 1u);
                mma_bf16_ss(tmem + 128, dAh + o, dBh1 + o, MMA_IDESC, en0);
                mma_bf16_ss(tmem + 128, dAh + o, dBl1 + o, MMA_IDESC, 1u);
                mma_bf16_ss(tmem + 128, dAl + o, dBh1 + o, MMA_IDESC, 1u);
            }
            TC_COMMIT(eb);
        }
        // each empty mbar: 6 commits; phases 0..4 consumed in-loop -> wait phase 5 (parity 1)
        mbar_wait(sb + 32, 1);
        mbar_wait(sb + 40, 1);
    }
    __syncthreads();
    TC_FENCE_AFTER();

    // epilogue: 8 warps; warp w: rows (w&3)*32+lane, cols (w>>2)*128..+128
    int sub = wid & 3, half = wid >> 2;
    int rowg = blockIdx.y * 128 + sub * 32 + lane;
    float* crow = C + (size_t)rowg * G3 + blockIdx.x * 256 + half * 128;
    #pragma unroll
    for (int part = 0; part < 2; part++) {
        uint32_t r0[32], r1[32];
        TC_LD_X32(r0, tmem + half * 128 + part * 64);
        TC_LD_X32(r1, tmem + half * 128 + part * 64 + 32);
        TC_WAIT_LD();
        #pragma unroll
        for (int c = 0; c < 32; c += 4) {
            *(float4*)(crow + part*64 + c) = make_float4(
                __uint_as_float(r0[c]),   __uint_as_float(r0[c+1]),
                __uint_as_float(r0[c+2]), __uint_as_float(r0[c+3]));
            *(float4*)(crow + part*64 + 32 + c) = make_float4(
                __uint_as_float(r1[c]),   __uint_as_float(r1[c+1]),
                __uint_as_float(r1[c+2]), __uint_as_float(r1[c+3]));
        }
    }
    TC_FENCE_BEFORE();
    __syncthreads();
    if (tid == 0) {
        mbar_inval(sb+16); mbar_inval(sb+24);
        mbar_inval(sb+32); mbar_inval(sb+40);
    }
    __syncthreads();
    if (wid == 0) { TC_RELINQUISH(); TC_DEALLOC(tmem, 512); }
#else
    // ---------------- FFMA fallback (plain sm_103 pass only) ----------------
    float* As = (float*)smem;              // [16][128]
    float* Bs = As + 16 * 128;

    int ty = tid >> 4, tx = tid & 15;
    const __nv_bfloat16* Ahb = Ahg + (size_t)blockIdx.y * 128 * HH;
    const __nv_bfloat16* Alb = Alg + (size_t)blockIdx.y * 128 * HH;

    for (int nb = 0; nb < 2; nb++) {
        const __nv_bfloat16* Bhb = Bhg + (size_t)(blockIdx.x * 256 + nb * 128) * HH;
        const __nv_bfloat16* Blb = Blg + (size_t)(blockIdx.x * 256 + nb * 128) * HH;
        float acc[8][8];
        #pragma unroll
        for (int i = 0; i < 8; i++)
            #pragma unroll
            for (int j = 0; j < 8; j++) acc[i][j] = 0.0f;

        for (int kt = 0; kt < HH; kt += 16) {
            {
                int r = tid >> 1, kq = (tid & 1) * 8;
                size_t go = (size_t)r * HH + kt + kq;
                uint4 vh = *(const uint4*)(Ahb + go);
                uint4 vl = *(const uint4*)(Alb + go);
                const __nv_bfloat16* ph = (const __nv_bfloat16*)&vh;
                const __nv_bfloat16* pl = (const __nv_bfloat16*)&vl;
                #pragma unroll
                for (int e = 0; e < 8; e++)
                    As[(kq + e) * 128 + r] = __bfloat162float(ph[e]) + __bfloat162float(pl[e]);
            }
            {
                int n = tid >> 1, kq = (tid & 1) * 8;
                size_t go = (size_t)n * HH + kt + kq;
                uint4 vh = *(const uint4*)(Bhb + go);
                uint4 vl = *(const uint4*)(Blb + go);
                const __nv_bfloat16* ph = (const __nv_bfloat16*)&vh;
                const __nv_bfloat16* pl = (const __nv_bfloat16*)&vl;
                #pragma unroll
                for (int e = 0; e < 8; e++)
                    Bs[(kq + e) * 128 + n] = __bfloat162float(ph[e]) + __bfloat162float(pl[e]);
            }
            __syncthreads();
            #pragma unroll
            for (int k = 0; k < 16; k++) {
                float ar[8], br[8];
                #pragma unroll
                for (int e = 0; e < 8; e++) ar[e] = As[k * 128 + ty * 8 + e];
                #pragma unroll
                for (int e = 0; e < 8; e++) br[e] = Bs[k * 128 + tx * 8 + e];
                #pragma unroll
                for (int i = 0; i < 8; i++)
                    #pragma unroll
                    for (int j = 0; j < 8; j++)
                        acc[i][j] = fmaf(ar[i], br[j], acc[i][j]);
            }
            __syncthreads();
        }
        int rowBase = blockIdx.y * 128 + ty * 8;
        int colBase = blockIdx.x * 256 + nb * 128 + tx * 8;
        #pragma unroll
        for (int i = 0; i < 8; i++) {
            *(float4*)(C + (size_t)(rowBase + i) * G3 + colBase) =
                make_float4(acc[i][0], acc[i][1], acc[i][2], acc[i][3]);
            *(float4*)(C + (size_t)(rowBase + i) * G3 + colBase + 4) =
                make_float4(acc[i][4], acc[i][5], acc[i][6], acc[i][7]);
        }
        __syncthreads();
    }
#endif
}

// ---------------- tiny utility kernels ----------------
__global__ void zero_kernel(float* p, int n) {
    int i = blockIdx.x * blockDim.x + threadIdx.x;
    if (i < n) p[i] = 0.0f;
}

__global__ void conv_bf16(const float* __restrict__ W, int ld, int off,
                          __nv_bfloat16* __restrict__ hi, __nv_bfloat16* __restrict__ lo) {
    int idx = blockIdx.x * blockDim.x + threadIdx.x;
    if (idx >= G3 * HH) return;
    int j = idx / HH, k = idx % HH;
    float x = W[(size_t)j * ld + off + k];
    __nv_bfloat16 h = __float2bfloat16(x);
    hi[idx] = h;
    lo[idx] = __float2bfloat16(x - __bfloat162float(h));
}

__global__ void prep_combined(const float* __restrict__ Wih, int ldw,
                              const float* __restrict__ bih,
                              const float* __restrict__ embW,
                              const float* __restrict__ embB,
                              float* __restrict__ Mout, float* __restrict__ bout) {
    int j = blockIdx.x * blockDim.x + threadIdx.x;
    if (j >= G3) return;
    float accM[DD];
    #pragma unroll
    for (int d = 0; d < DD; d++) accM[d] = 0.0f;
    float accb = 0.0f;
    const float* wrow = Wih + (size_t)j * ldw;
    for (int e = 0; e < EE; e++) {
        float w = wrow[e];
        accb += embB[e] * w;
        const float* er = embW + e * DD;
        #pragma unroll
        for (int d = 0; d < DD; d++) accM[d] += er[d] * w;
    }
    #pragma unroll
    for (int d = 0; d < DD; d++) Mout[d * G3 + j] = SCALEF * accM[d];
    bout[j] = accb + bih[j];
}

// ---------------- fused GRU update ----------------
__global__ void gru_update(const float* __restrict__ Mm, const float* __restrict__ bvec,
                           const float* __restrict__ bhh, const float* __restrict__ C2,
                           const float* __restrict__ G,
                           const float* __restrict__ pa, const float* __restrict__ pb,
                           float* __restrict__ h,
                           __nv_bfloat16* __restrict__ ah, __nv_bfloat16* __restrict__ al) {
    int j = blockIdx.x * blockDim.x + threadIdx.x;
    int row = blockIdx.y;

    __shared__ float vs[DD];
    if (threadIdx.x < DD)
        vs[threadIdx.x] = pa[row * DD + threadIdx.x] - pb[row * DD + threadIdx.x];
    __syncthreads();

    float gi_r = bvec[j];
    float gi_z = bvec[j + HH];
    float gi_n = bvec[j + 2 * HH];
    #pragma unroll
    for (int d = 0; d < DD; d++) {
        float vd = vs[d];
        gi_r = fmaf(vd, Mm[d * G3 + j],          gi_r);
        gi_z = fmaf(vd, Mm[d * G3 + j + HH],     gi_z);
        gi_n = fmaf(vd, Mm[d * G3 + j + 2 * HH], gi_n);
    }
    if (C2 != nullptr) {
        const float* c = C2 + (size_t)row * G3;
        gi_r += c[j];
        gi_z += c[j + HH];
        gi_n += c[j + 2 * HH];
    }
    float gh_r, gh_z, gh_n;
    if (G != nullptr) {
        const float* grow = G + (size_t)row * G3;
        gh_r = grow[j]          + bhh[j];
        gh_z = grow[j + HH]     + bhh[j + HH];
        gh_n = grow[j + 2 * HH] + bhh[j + 2 * HH];
    } else {
        gh_r = bhh[j];
        gh_z = bhh[j + HH];
        gh_n = bhh[j + 2 * HH];
    }

    float r = 1.0f / (1.0f + expf(-(gi_r + gh_r)));
    float z = 1.0f / (1.0f + expf(-(gi_z + gh_z)));
    float n = tanhf(gi_n + r * gh_n);
    size_t idx = (size_t)row * HH + j;
    float ho = h[idx];
    float hn = (1.0f - z) * n + z * ho;
    h[idx] = hn;
    __nv_bfloat16 hb = __float2bfloat16(hn);
    ah[idx] = hb;
    al[idx] = __float2bfloat16(hn - __bfloat162float(hb));
}

// ---------------- decoder head ----------------
__global__ void h2n_pos(const float* __restrict__ h,
                        const float* __restrict__ h2nW, const float* __restrict__ h2nB,
                        const float* __restrict__ mixW, const float* __restrict__ mixB,
                        const float* __restrict__ base,
                        float* __restrict__ out_rel, float* __restrict__ out_pos) {
    int row = blockIdx.x;
    int tid = threadIdx.x;
    int warp = tid >> 5, lane = tid & 31;
    __shared__ float sn[5];
    if (warp < 5) {
        const float* hr = h + (size_t)row * HH;
        const float* wr = h2nW + warp * HH;
        float s = 0.0f;
        for (int i = lane; i < HH; i += 32) s = fmaf(hr[i], wr[i], s);
        #pragma unroll
        for (int o = 16; o > 0; o >>= 1) s += __shfl_down_sync(0xffffffffu, s, o);
        if (lane == 0) {
            float raw = s + h2nB[warp];
            float val;
            if (warp < 2) val = raw;
            else if (warp < 4) {
                float sp = raw > 0.0f ? raw + log1pf(expf(-raw)) : log1pf(expf(raw));
                val = 0.01f + 0.2f * sp;
            } else val = 0.7f * tanhf(raw);
            sn[warp] = val;
            out_rel[(size_t)row * 5 + warp] = val;
        }
    }
    __syncthreads();
    if (tid < DD) {
        float acc = mixB[tid];
        #pragma unroll
        for (int c = 0; c < 5; c++) acc = fmaf(sn[c], mixW[tid * 5 + c], acc);
        acc = acc > 0.0f ? acc : 0.0f;
        out_pos[(size_t)row * DD + tid] = base[(size_t)row * DD + tid] + acc;
    }
}

// ---------------- host: tensor-map creation via driver entry point ----------
typedef CUresult (*PFN_tmEncode)(CUtensorMap*, CUtensorMapDataType, cuuint32_t, void*,
                                 const cuuint64_t*, const cuuint64_t*, const cuuint32_t*,
                                 const cuuint32_t*, CUtensorMapInterleave, CUtensorMapSwizzle,
                                 CUtensorMapL2promotion, CUtensorMapFloatOOBfill);

static PFN_tmEncode tm_encode_fn() {
    static PFN_tmEncode fn = nullptr;
    if (!fn) {
        void* p = nullptr;
        cudaDriverEntryPointQueryResult qr;
        cudaGetDriverEntryPoint("cuTensorMapEncodeTiled", &p, cudaEnableDefault, &qr);
        fn = (PFN_tmEncode)p;
    }
    return fn;
}

static void make_map_bf16(CUtensorMap* m, void* ptr, int rows) {
    cuuint64_t dims[2]    = {(cuuint64_t)HH, (cuuint64_t)rows};
    cuuint64_t strides[1] = {(cuuint64_t)HH * 2};
    cuuint32_t box[2]     = {64, 128};
    cuuint32_t es[2]      = {1, 1};
    tm_encode_fn()(m, CU_TENSOR_MAP_DATA_TYPE_BFLOAT16, 2, ptr, dims, strides, box, es,
                   CU_TENSOR_MAP_INTERLEAVE_NONE, CU_TENSOR_MAP_SWIZZLE_128B,
                   CU_TENSOR_MAP_L2_PROMOTION_L2_128B, CU_TENSOR_MAP_FLOAT_OOB_FILL_NONE);
}

// ---------------- host orchestration ----------------
extern "C" void kernel_launch(void* const* d_in, const int* in_sizes, int n_in,
                              void* d_out, int out_size) {
    const float* observed = (const float*)d_in[0];
    const float* emb_W    = (const float*)d_in[1];
    const float* emb_b    = (const float*)d_in[2];
    const float* e1_Wih   = (const float*)d_in[3];
    const float* e1_Whh   = (const float*)d_in[4];
    const float* e1_bih   = (const float*)d_in[5];
    const float* e1_bhh   = (const float*)d_in[6];
    const float* e2_Wih   = (const float*)d_in[7];
    const float* e2_Whh   = (const float*)d_in[8];
    const float* e2_bih   = (const float*)d_in[9];
    const float* e2_bhh   = (const float*)d_in[10];
    const float* dec_Wih  = (const float*)d_in[11];
    const float* dec_Whh  = (const float*)d_in[12];
    const float* dec_bih  = (const float*)d_in[13];
    const float* dec_bhh  = (const float*)d_in[14];
    const float* h2n_W    = (const float*)d_in[15];
    const float* h2n_b    = (const float*)d_in[16];
    const float* mix_W    = (const float*)d_in[17];
    const float* mix_b    = (const float*)d_in[18];
    float* out = (float*)d_out;

    float *M1, *M2, *Md, *b1, *b2, *bd, *C2, *G, *h;
    __nv_bfloat16 *Bh1, *Bl1, *Bh2, *Bl2, *Bhd, *Bld, *Bh2x, *Bl2x, *Ah, *Al;
    cudaGetSymbolAddress((void**)&M1,  g_M1);
    cudaGetSymbolAddress((void**)&M2,  g_M2);
    cudaGetSymbolAddress((void**)&Md,  g_Md);
    cudaGetSymbolAddress((void**)&b1,  g_b1);
    cudaGetSymbolAddress((void**)&b2,  g_b2);
    cudaGetSymbolAddress((void**)&bd,  g_bd);
    cudaGetSymbolAddress((void**)&Bh1, g_Bh1);
    cudaGetSymbolAddress((void**)&Bl1, g_Bl1);
    cudaGetSymbolAddress((void**)&Bh2, g_Bh2);
    cudaGetSymbolAddress((void**)&Bl2, g_Bl2);
    cudaGetSymbolAddress((void**)&Bhd, g_Bhd);
    cudaGetSymbolAddress((void**)&Bld, g_Bld);
    cudaGetSymbolAddress((void**)&Bh2x,g_Bh2x);
    cudaGetSymbolAddress((void**)&Bl2x,g_Bl2x);
    cudaGetSymbolAddress((void**)&Ah,  g_Ah);
    cudaGetSymbolAddress((void**)&Al,  g_Al);
    cudaGetSymbolAddress((void**)&C2,  g_C2);
    cudaGetSymbolAddress((void**)&G,   g_G);
    cudaGetSymbolAddress((void**)&h,   g_h);

    // tensor maps (host-side structs; passed by value into each launch)
    CUtensorMap tAh, tAl, tB1h, tB1l, tB2h, tB2l, tBdh, tBdl, tB2xh, tB2xl;
    make_map_bf16(&tAh,  Ah,  NB);
    make_map_bf16(&tAl,  Al,  NB);
    make_map_bf16(&tB1h, Bh1, G3);
    make_map_bf16(&tB1l, Bl1, G3);
    make_map_bf16(&tB2h, Bh2, G3);
    make_map_bf16(&tB2l, Bl2, G3);
    make_map_bf16(&tBdh, Bhd, G3);
    make_map_bf16(&tBdl, Bld, G3);
    make_map_bf16(&tB2xh, Bh2x, G3);
    make_map_bf16(&tB2xl, Bl2x, G3);

    cudaFuncSetAttribute(gemm_tc, cudaFuncAttributeMaxDynamicSharedMemorySize, GEMM_SMEM);

    const int ND = NB * DD;
    const int NH = NB * HH;
    float* rel_out  = out;
    float* pred_out = out + (size_t)NPRED * NB * 5;

    dim3 gemmGrid(G3 / 256, NB / 128);   // (9,16)
    dim3 gruGrid(HH / 256, NB);          // (3,2048)
    const int WELEM = G3 * HH;

    prep_combined<<<(G3 + 255) / 256, 256>>>(e1_Wih,  EE,      e1_bih,  emb_W, emb_b, M1, b1);
    prep_combined<<<(G3 + 255) / 256, 256>>>(e2_Wih,  EE + HH, e2_bih,  emb_W, emb_b, M2, b2);
    prep_combined<<<(G3 + 255) / 256, 256>>>(dec_Wih, EE,      dec_bih, emb_W, emb_b, Md, bd);

    conv_bf16<<<(WELEM + 255) / 256, 256>>>(e1_Whh,  HH,      0,  Bh1,  Bl1);
    conv_bf16<<<(WELEM + 255) / 256, 256>>>(e2_Whh,  HH,      0,  Bh2,  Bl2);
    conv_bf16<<<(WELEM + 255) / 256, 256>>>(dec_Whh, HH,      0,  Bhd,  Bld);
    conv_bf16<<<(WELEM + 255) / 256, 256>>>(e2_Wih,  EE + HH, EE, Bh2x, Bl2x);

    zero_kernel<<<(NH + 255) / 256, 256>>>(h, NH);

    // ---- encoder 1 ----
    for (int t = 0; t < TT - 1; t++) {
        const float* pa = observed + (size_t)(7 - t) * ND;
        const float* pb = observed + (size_t)(6 - t) * ND;
        const float* Gp = nullptr;
        if (t > 0) {
            gemm_tc<<<gemmGrid, 256, GEMM_SMEM>>>(tAh, tAl, tB1h, tB1l, Ah, Al, Bh1, Bl1, G);
            Gp = G;
        }
        gru_update<<<gruGrid, 256>>>(M1, b1, e1_bhh, nullptr, Gp, pa, pb, h, Ah, Al);
    }

    // C2 = h_inv @ e2_Wih[:,256:]^T
    gemm_tc<<<gemmGrid, 256, GEMM_SMEM>>>(tAh, tAl, tB2xh, tB2xl, Ah, Al, Bh2x, Bl2x, C2);

    zero_kernel<<<(NH + 255) / 256, 256>>>(h, NH);

    // ---- encoder 2 ----
    for (int t = 0; t < TT - 1; t++) {
        const float* pa = observed + (size_t)(t + 1) * ND;
        const float* pb = observed + (size_t)t * ND;
        const float* Gp = nullptr;
        if (t > 0) {
            gemm_tc<<<gemmGrid, 256, GEMM_SMEM>>>(tAh, tAl, tB2h, tB2l, Ah, Al, Bh2, Bl2, G);
            Gp = G;
        }
        gru_update<<<gruGrid, 256>>>(M2, b2, e2_bhh, C2, Gp, pa, pb, h, Ah, Al);
    }

    // ---- decoder ----
    for (int k = 0; k < NPRED; k++) {
        const float *pa, *pb;
        if (k == 0)      { pa = observed + (size_t)7 * ND; pb = observed + (size_t)6 * ND; }
        else if (k == 1) { pa = pred_out;                  pb = observed + (size_t)7 * ND; }
        else             { pa = pred_out + (size_t)(k-1)*ND; pb = pred_out + (size_t)(k-2)*ND; }
        gemm_tc<<<gemmGrid, 256, GEMM_SMEM>>>(tAh, tAl, tBdh, tBdl, Ah, Al, Bhd, Bld, G);
        gru_update<<<gruGrid, 256>>>(Md, bd, dec_bhh, nullptr, G, pa, pb, h, Ah, Al);
        h2n_pos<<<NB, 160>>>(h, h2n_W, h2n_b, mix_W, mix_b, pa,
                             rel_out + (size_t)k * NB * 5,
                             pred_out + (size_t)k * ND);
    }
}